// round 17
// baseline (speedup 1.0000x reference)
#include <cuda_runtime.h>
#include <cuda_fp16.h>
#include <math.h>
#include <stdint.h>

#define B_ROWS 16384
#define C_CLS  1000
#define F_DIM  256

#define BM 128
#define BN 128
#define BK 32                   // k elements per chunk
#define NCHUNK (F_DIM / BK)     // 8
#define LDH 40                  // fp16 smem row stride (halves)
#define LDS32 36                // fp32 stage row stride (floats), 144B = 16B-aligned

// smem layout (bytes)
#define H16_OFF 0                        // 2 bufs x (A 10240 + B 10240) = 40960
#define HBUF_SZ 20480
#define STG_A   40960                    // 128*36*4 = 18432
#define STG_B   59392                    // 18432
#define PRM_SHS 77824                    // 128 floats each
#define PRM_LCS 78336
#define PRM_ISC 78848
#define PRM_F2  79360
#define PRM_M2  79872
#define SMEM_BYTES 80384

// ---- device scratch ----
__device__ __half g_escores[(size_t)B_ROWS * C_CLS];   // fp16 exp(score)

__device__ __forceinline__ uint32_t smem_u32(const void* p) {
    uint32_t a;
    asm("{ .reg .u64 t; cvta.to.shared.u64 t, %1; cvt.u32.u64 %0, t; }" : "=r"(a) : "l"(p));
    return a;
}
__device__ __forceinline__ void cp16(uint32_t daddr, const void* src, uint32_t bytes) {
    asm volatile("cp.async.ca.shared.global [%0], [%1], 16, %2;"
                 :: "r"(daddr), "l"(src), "r"(bytes) : "memory");
}
__device__ __forceinline__ void mma_f16(float* d, const uint32_t* a, const uint32_t* b) {
    asm volatile(
        "mma.sync.aligned.m16n8k16.row.col.f32.f16.f16.f32 "
        "{%0,%1,%2,%3}, {%4,%5,%6,%7}, {%8,%9}, {%0,%1,%2,%3};"
        : "+f"(d[0]), "+f"(d[1]), "+f"(d[2]), "+f"(d[3])
        : "r"(a[0]), "r"(a[1]), "r"(a[2]), "r"(a[3]), "r"(b[0]), "r"(b[1]));
}

// -------------------------------------------------------------------------
// Fused GEMM: cp.async fp32 stage -> in-smem fp16 convert (+reg sumsq) ->
// fp16 mma.sync -> OpenMax epilogue storing exp(score) fp16.
// 256 threads, CTA tile 128x128, BK=32.
// -------------------------------------------------------------------------
__global__ void __launch_bounds__(256, 2)
gemm_openmax_fused(const float* __restrict__ featF,
                   const float* __restrict__ meanF,
                   const float* __restrict__ logits,
                   const float* __restrict__ wshape,
                   const float* __restrict__ wloc,
                   const float* __restrict__ wscale) {
    extern __shared__ char smem[];
    const uint32_t sb = smem_u32(smem);
    const int tid = threadIdx.x;
    const int lane = tid & 31;
    const int wid = tid >> 5;
    const int wm = wid & 1;
    const int wn = wid >> 1;
    const int rowBase = blockIdx.y * BM;
    const int colBase = blockIdx.x * BN;

    float* shs  = (float*)(smem + PRM_SHS);
    float* lcs  = (float*)(smem + PRM_LCS);
    float* iscs = (float*)(smem + PRM_ISC);
    float* f2s  = (float*)(smem + PRM_F2);
    float* m2s  = (float*)(smem + PRM_M2);
    if (tid < 128) {
        int gc = colBase + tid;
        int cc = (gc < C_CLS) ? gc : 0;
        shs[tid] = wshape[cc];
        lcs[tid] = wloc[cc];
        iscs[tid] = 1.f / wscale[cc];
    }

    // ---- fp32 chunk stage loader (A + B), single stage buffer ----
    auto stage32 = [&](int ch) {
        const int k0 = ch * BK;
#pragma unroll
        for (int i = 0; i < 4; i++) {
            int idx = tid + i * 256;          // 0..1023
            int r = idx >> 3;                 // 0..127
            int c4 = (idx & 7) * 4;           // 0,4,...,28
            cp16(sb + STG_A + (uint32_t)(r * LDS32 + c4) * 4,
                 featF + (size_t)(rowBase + r) * F_DIM + k0 + c4, 16u);
        }
#pragma unroll
        for (int i = 0; i < 4; i++) {
            int idx = tid + i * 256;
            int r = idx >> 3;
            int c4 = (idx & 7) * 4;
            int gc = colBase + r;
            cp16(sb + STG_B + (uint32_t)(r * LDS32 + c4) * 4,
                 meanF + (size_t)((gc < C_CLS) ? gc : 0) * F_DIM + k0 + c4,
                 (gc < C_CLS) ? 16u : 0u);
        }
        asm volatile("cp.async.commit_group;" ::: "memory");
    };

    // per-thread sumsq accumulators: iter i covers row (tid>>3)+32i, invariant
    float sA[4] = {0.f, 0.f, 0.f, 0.f};
    float sB[4] = {0.f, 0.f, 0.f, 0.f};

    // ---- fp32 stage -> fp16 buffer conversion (+ sumsq accumulation) ----
    auto cvt = [&](int buf) {
        char* hA = smem + H16_OFF + buf * HBUF_SZ;
        char* hB = hA + 10240;
#pragma unroll
        for (int i = 0; i < 4; i++) {
            int idx = tid + i * 256;
            int r = idx >> 3;
            int c4 = (idx & 7) * 4;
            float4 va = *(const float4*)(smem + STG_A + (r * LDS32 + c4) * 4);
            sA[i] += va.x * va.x + va.y * va.y + va.z * va.z + va.w * va.w;
            __half2 a0 = __floats2half2_rn(va.x, va.y);
            __half2 a1 = __floats2half2_rn(va.z, va.w);
            uint2 ua; ua.x = *(uint32_t*)&a0; ua.y = *(uint32_t*)&a1;
            *(uint2*)(hA + (r * LDH + c4) * 2) = ua;

            float4 vb = *(const float4*)(smem + STG_B + (r * LDS32 + c4) * 4);
            sB[i] += vb.x * vb.x + vb.y * vb.y + vb.z * vb.z + vb.w * vb.w;
            __half2 b0 = __floats2half2_rn(vb.x, vb.y);
            __half2 b1 = __floats2half2_rn(vb.z, vb.w);
            uint2 ub; ub.x = *(uint32_t*)&b0; ub.y = *(uint32_t*)&b1;
            *(uint2*)(hB + (r * LDH + c4) * 2) = ub;
        }
    };

    float acc[4][4][4];
#pragma unroll
    for (int i = 0; i < 4; i++)
#pragma unroll
        for (int j = 0; j < 4; j++)
#pragma unroll
            for (int q = 0; q < 4; q++) acc[i][j][q] = 0.f;

    // ---- prologue ----
    stage32(0);
    asm volatile("cp.async.wait_group 0;" ::: "memory");
    __syncthreads();
    cvt(0);
    __syncthreads();
    stage32(1);

    const int g = lane >> 2;
    const int kq = lane & 3;
    const int lq = lane & 3;
    const int lr = lane >> 2;
    const int r0 = wm * 64 + g;
    const int c0 = wn * 32 + g;

#pragma unroll 1
    for (int ch = 0; ch < NCHUNK; ch++) {
        const char* hA = smem + H16_OFF + (ch & 1) * HBUF_SZ;
        const __half* A = (const __half*)hA;
        const __half* Bs = (const __half*)(hA + 10240);
#pragma unroll
        for (int ks = 0; ks < 2; ks++) {
            const int kb = ks * 16 + 2 * kq;
            uint32_t a[4][4], b[4][2];
#pragma unroll
            for (int ma = 0; ma < 4; ma++) {
                const __half* ap = A + (r0 + ma * 16) * LDH + kb;
                a[ma][0] = *(const uint32_t*)(ap);
                a[ma][1] = *(const uint32_t*)(ap + 8 * LDH);
                a[ma][2] = *(const uint32_t*)(ap + 8);
                a[ma][3] = *(const uint32_t*)(ap + 8 * LDH + 8);
            }
#pragma unroll
            for (int na = 0; na < 4; na++) {
                const __half* bp = Bs + (c0 + na * 8) * LDH + kb;
                b[na][0] = *(const uint32_t*)(bp);
                b[na][1] = *(const uint32_t*)(bp + 8);
            }
#pragma unroll
            for (int ma = 0; ma < 4; ma++)
#pragma unroll
                for (int na = 0; na < 4; na++)
                    mma_f16(acc[ma][na], a[ma], b[na]);
        }

        if (ch < NCHUNK - 1) {
            asm volatile("cp.async.wait_group 0;" ::: "memory");
            __syncthreads();                 // fragment LDS done; stage ready
            cvt((ch + 1) & 1);
            __syncthreads();                 // fp16 visible; stage reusable
            if (ch < NCHUNK - 2) stage32(ch + 2);
        }
    }

    // ---- reduce sumsq (8 threads per row, within-warp shuffles) ----
#pragma unroll
    for (int i = 0; i < 4; i++) {
#pragma unroll
        for (int o = 1; o < 8; o <<= 1) {
            sA[i] += __shfl_xor_sync(0xffffffffu, sA[i], o);
            sB[i] += __shfl_xor_sync(0xffffffffu, sB[i], o);
        }
    }
    if ((tid & 7) == 0) {
        const int rbase = tid >> 3;          // 0..31
#pragma unroll
        for (int i = 0; i < 4; i++) {
            f2s[rbase + 32 * i] = sA[i];
            m2s[rbase + 32 * i] = sB[i];
        }
    }
    __syncthreads();

    // ---- fused OpenMax epilogue: store exp(score) as fp16 ----
#pragma unroll
    for (int ma = 0; ma < 4; ma++) {
#pragma unroll
        for (int h = 0; h < 2; h++) {
            const int lrow = wm * 64 + ma * 16 + lr + h * 8;
            const int grow = rowBase + lrow;
            const float f2v = f2s[lrow];
            const float* lrowp = logits + (size_t)grow * C_CLS;
            __half* erow = g_escores + (size_t)grow * C_CLS;
#pragma unroll
            for (int na = 0; na < 4; na++) {
                const int col = wn * 32 + na * 8 + 2 * lq;
                const int gc = colBase + col;
                if (gc >= C_CLS) continue;
                float2 lg = *(const float2*)(lrowp + gc);
                float dots[2] = { acc[ma][na][h * 2], acc[ma][na][h * 2 + 1] };
                float lgv[2] = { lg.x, lg.y };
                float res[2];
#pragma unroll
                for (int q = 0; q < 2; q++) {
                    const int c = col + q;
                    float d2 = f2v + m2s[c] - 2.f * dots[q];
                    float dist = sqrtf(fmaxf(d2, 1e-12f));
                    float xp = (dist - lcs[c]) * iscs[c];
                    float wv = 0.f;
                    if (xp > 0.f) {
                        float p = exp2f(shs[c] * __log2f(xp));
                        wv = 1.f - __expf(-p);
                    }
                    float w2 = wv * wv;
                    float w4 = w2 * w2;
                    float w10 = w4 * w4 * w2;
                    res[q] = __expf(lgv[q] * (1.f - w10));
                }
                __half2 eh = __floats2half2_rn(res[0], res[1]);
                *(__half2*)(erow + gc) = eh;
            }
        }
    }
}

// -------------------------------------------------------------------------
// Softmax scale: e already exponentiated (fp16). 2 rows / 256-thread block.
// -------------------------------------------------------------------------
__global__ void __launch_bounds__(256)
softmax_kernel(float* __restrict__ out) {
    const int tid = threadIdx.x;
    const int half_id = tid >> 7;
    const int t = tid & 127;
    const int row = blockIdx.x * 2 + half_id;
    const bool act = (t < 125);

    float v[8];
    float s = 0.f;
    if (act) {
        uint4 u = *(const uint4*)(g_escores + (size_t)row * C_CLS + t * 8);
        const __half2* hp = (const __half2*)&u;
#pragma unroll
        for (int i = 0; i < 4; i++) {
            float2 f = __half22float2(hp[i]);
            v[i * 2] = f.x;
            v[i * 2 + 1] = f.y;
            s += f.x + f.y;
        }
    } else {
#pragma unroll
        for (int i = 0; i < 8; i++) v[i] = 0.f;
    }
#pragma unroll
    for (int o = 16; o; o >>= 1) s += __shfl_xor_sync(0xffffffffu, s, o);

    __shared__ float red[8];
    if ((tid & 31) == 0) red[tid >> 5] = s;
    __syncthreads();
    float total = 0.f;
#pragma unroll
    for (int w = 0; w < 4; w++) total += red[half_id * 4 + w];
    const float inv = 1.f / total;

    if (act) {
        float* orow = out + (size_t)row * C_CLS + t * 8;
        float4 o0, o1;
        o0.x = v[0] * inv; o0.y = v[1] * inv; o0.z = v[2] * inv; o0.w = v[3] * inv;
        o1.x = v[4] * inv; o1.y = v[5] * inv; o1.z = v[6] * inv; o1.w = v[7] * inv;
        *(float4*)(orow) = o0;
        *(float4*)(orow + 4) = o1;
    }
}

// -------------------------------------------------------------------------
extern "C" void kernel_launch(void* const* d_in, const int* in_sizes, int n_in,
                              void* d_out, int out_size) {
    const float* logits    = (const float*)d_in[0];
    const float* features  = (const float*)d_in[1];
    const float* mean_vecs = (const float*)d_in[2];
    const float* wb_shape  = (const float*)d_in[3];
    const float* wb_loc    = (const float*)d_in[4];
    const float* wb_scale  = (const float*)d_in[5];
    float* out = (float*)d_out;

    cudaFuncSetAttribute(gemm_openmax_fused,
                         cudaFuncAttributeMaxDynamicSharedMemorySize, SMEM_BYTES);

    dim3 grid((C_CLS + BN - 1) / BN, B_ROWS / BM);   // (8, 128)
    gemm_openmax_fused<<<grid, 256, SMEM_BYTES>>>(features, mean_vecs, logits,
                                                  wb_shape, wb_loc, wb_scale);

    softmax_kernel<<<B_ROWS / 2, 256>>>(out);
    (void)in_sizes; (void)n_in; (void)out_size;
}